// round 2
// baseline (speedup 1.0000x reference)
#include <cuda_runtime.h>
#include <math.h>

#define Bb 8
#define Cc 256
#define Ll 512
#define NG 32
#define NH 8
#define Ee 1024
#define NTOK (Bb*Cc)

// ---------------- scratch (device globals; no dynamic alloc) ----------------
__device__ float g_S1[Bb*Cc*Ll];
__device__ float g_S2[Bb*Cc*Ll];
__device__ float g_S3[Bb*Cc*Ll];
__device__ float g_T [Bb*Ll*768];      // qkv buffer; reused for final conv out
__device__ float g_stats[Bb*NG*2];
__device__ float g_rawsum[Bb*Ee];
__device__ int   g_cnt1[Bb*Ee];
__device__ int   g_idx1[NTOK];
__device__ int   g_idx2[NTOK];
__device__ float g_g1[NTOK];
__device__ float g_g2[NTOK];

__device__ __forceinline__ float gelu_f(float x) {
    return 0.5f * x * (1.0f + erff(x * 0.70710678118654752f));
}

// ---------------- elementwise add ----------------
__global__ void add_k(const float* __restrict__ x, const float* __restrict__ e, float* __restrict__ o) {
    int i = blockIdx.x * 256 + threadIdx.x;
    o[i] = x[i] + e[i];
}

// ---------------- groupnorm stats: one block per (b,g); group = contiguous 4096 floats ----------------
__global__ void gnstats_k(const float* __restrict__ in) {
    __shared__ float rs[256], rq[256];
    int bg = blockIdx.x;
    const float* p = in + bg * 4096;
    float s = 0.f, q = 0.f;
    for (int i = threadIdx.x; i < 4096; i += 256) { float v = p[i]; s += v; q += v * v; }
    rs[threadIdx.x] = s; rq[threadIdx.x] = q;
    __syncthreads();
    for (int st = 128; st > 0; st >>= 1) {
        if (threadIdx.x < st) { rs[threadIdx.x] += rs[threadIdx.x + st]; rq[threadIdx.x] += rq[threadIdx.x + st]; }
        __syncthreads();
    }
    if (threadIdx.x == 0) {
        float mean = rs[0] * (1.f / 4096.f);
        float var  = rq[0] * (1.f / 4096.f) - mean * mean;
        g_stats[bg * 2]     = mean;
        g_stats[bg * 2 + 1] = rsqrtf(var + 1e-5f);
    }
}

// ---------------- groupnorm apply + gelu ----------------
__global__ void gngelu_k(const float* __restrict__ in, const float* __restrict__ sc,
                         const float* __restrict__ bi, float* __restrict__ out) {
    int i = blockIdx.x * 256 + threadIdx.x;
    int c = (i >> 9) & 255;
    int b = i >> 17;
    int bg = b * 32 + (c >> 3);
    float mean = g_stats[bg * 2], rstd = g_stats[bg * 2 + 1];
    float v = (in[i] - mean) * rstd * sc[c] + bi[c];
    out[i] = gelu_f(v);
}

// ---------------- conv1d k=3, Cin=256, 4 output channels per block, weights in smem ----------------
__global__ __launch_bounds__(128) void conv3_k(
    const float* __restrict__ in, const float* __restrict__ w, const float* __restrict__ bias,
    const float* __restrict__ resid, float* __restrict__ out, int Cout) {
    __shared__ float ws[4 * 256 * 3];
    int b = blockIdx.z, co0 = blockIdx.y * 4;
    int l = blockIdx.x * 128 + threadIdx.x;
    for (int i = threadIdx.x; i < 4 * 256 * 3; i += 128) ws[i] = w[co0 * 768 + i];
    __syncthreads();
    float a0 = bias[co0], a1 = bias[co0 + 1], a2 = bias[co0 + 2], a3 = bias[co0 + 3];
    const float* ip = in + b * 256 * 512;
    #pragma unroll 2
    for (int ci = 0; ci < 256; ci++) {
        const float* row = ip + ci * 512;
        float xm = (l > 0)   ? row[l - 1] : 0.f;
        float x0 = row[l];
        float xp = (l < 511) ? row[l + 1] : 0.f;
        const float* wp = ws + ci * 3;
        a0 += xm * wp[0]    + x0 * wp[1]    + xp * wp[2];
        a1 += xm * wp[768]  + x0 * wp[769]  + xp * wp[770];
        a2 += xm * wp[1536] + x0 * wp[1537] + xp * wp[1538];
        a3 += xm * wp[2304] + x0 * wp[2305] + xp * wp[2306];
    }
    int o0 = (b * Cout + co0) * 512 + l;
    if (resid) {
        out[o0]        = a0 + resid[o0];
        out[o0 + 512]  = a1 + resid[o0 + 512];
        out[o0 + 1024] = a2 + resid[o0 + 1024];
        out[o0 + 1536] = a3 + resid[o0 + 1536];
    } else {
        out[o0] = a0; out[o0 + 512] = a1; out[o0 + 1024] = a2; out[o0 + 1536] = a3;
    }
}

// ---------------- QKV: T[b,l,f] = sum_c x[b,c,l] * w1[c,f] + b1[f] ----------------
__global__ __launch_bounds__(256) void qkv_k(const float* __restrict__ x, const float* __restrict__ w1,
                                             const float* __restrict__ b1, float* __restrict__ T) {
    __shared__ float xs[256][32];
    int b = blockIdx.x, l0 = blockIdx.y * 32;
    for (int i = threadIdx.x; i < 256 * 32; i += 256) {
        int c = i >> 5, j = i & 31;
        xs[c][j] = x[(b * 256 + c) * 512 + l0 + j];
    }
    __syncthreads();
    for (int jf = 0; jf < 3; jf++) {
        int f = jf * 256 + threadIdx.x;
        float acc[32];
        float bb = b1[f];
        #pragma unroll
        for (int j = 0; j < 32; j++) acc[j] = bb;
        for (int c = 0; c < 256; c++) {
            float wv = w1[c * 768 + f];
            #pragma unroll
            for (int j = 0; j < 32; j++) acc[j] += xs[c][j] * wv;
        }
        #pragma unroll
        for (int j = 0; j < 32; j++) T[(b * 512 + l0 + j) * 768 + f] = acc[j];
    }
}

// ---------------- attention: one CTA per (b,h); K,V in smem; thread per q-row, online softmax ----------------
__global__ __launch_bounds__(512) void attn_k(const float* __restrict__ T, float* __restrict__ O) {
    extern __shared__ float sm[];
    float* Ks = sm;
    float* Vs = sm + 512 * 32;
    int b = blockIdx.x, h = blockIdx.y, tid = threadIdx.x;
    for (int i = tid; i < 512 * 32; i += 512) {
        int k = i >> 5, d = i & 31;
        const float* base = T + (b * 512 + k) * 768 + (d * 24 + h * 3);
        Ks[i] = base[1];
        Vs[i] = base[2];
    }
    __syncthreads();
    float q[32];
    {
        const float* base = T + (b * 512 + tid) * 768 + h * 3;
        #pragma unroll
        for (int d = 0; d < 32; d++) q[d] = base[d * 24];
    }
    float m = -1e30f, s = 0.f, acc[32];
    #pragma unroll
    for (int d = 0; d < 32; d++) acc[d] = 0.f;
    const float scale = 0.17677669529663687f; // 1/sqrt(32)
    for (int k = 0; k < 512; k++) {
        float dot = 0.f;
        const float* kr = Ks + k * 32;
        #pragma unroll
        for (int d = 0; d < 32; d++) dot += q[d] * kr[d];
        dot *= scale;
        float mn = fmaxf(m, dot);
        float corr = __expf(m - mn);
        float p = __expf(dot - mn);
        s = s * corr + p;
        const float* vr = Vs + k * 32;
        #pragma unroll
        for (int d = 0; d < 32; d++) acc[d] = acc[d] * corr + p * vr[d];
        m = mn;
    }
    float inv = 1.f / s;
    float* op = O + (b * 512 + tid) * 256 + h;
    #pragma unroll
    for (int d = 0; d < 32; d++) op[d * 8] = acc[d] * inv;
}

// ---------------- out projection + transpose + embeddings add (start of res_block2) ----------------
__global__ __launch_bounds__(256) void oproj_k(const float* __restrict__ O, const float* __restrict__ w2,
                                               const float* __restrict__ b2, const float* __restrict__ emb,
                                               float* __restrict__ out) {
    __shared__ float os[32][256];
    int b = blockIdx.x, l0 = blockIdx.y * 32;
    for (int i = threadIdx.x; i < 32 * 256; i += 256) {
        int j = i >> 8, c = i & 255;
        os[j][c] = O[(b * 512 + l0 + j) * 256 + c];
    }
    __syncthreads();
    int co = threadIdx.x;
    float acc[32];
    float bb = b2[co];
    #pragma unroll
    for (int j = 0; j < 32; j++) acc[j] = bb;
    for (int c = 0; c < 256; c++) {
        float wv = w2[c * 256 + co];
        #pragma unroll
        for (int j = 0; j < 32; j++) acc[j] += os[j][c] * wv;
    }
    #pragma unroll
    for (int j = 0; j < 32; j++) {
        int oi = (b * 256 + co) * 512 + l0 + j;
        out[oi] = acc[j] + emb[oi];
    }
}

// ---------------- zero rawsum ----------------
__global__ void zero_k() {
    int i = blockIdx.x * 256 + threadIdx.x;
    if (i < Bb * Ee) g_rawsum[i] = 0.f;
}

// ---------------- gating: softmax over E=1024, top2, normalized gates, rawsum ----------------
__global__ __launch_bounds__(256) void gate_k(const float* __restrict__ X, const float* __restrict__ wg) {
    __shared__ float xv[512];
    __shared__ float red[256];
    __shared__ int redi[256];
    int t = blockIdx.x, tid = threadIdx.x, b = t >> 8;
    for (int i = tid; i < 512; i += 256) xv[i] = X[t * 512 + i];
    __syncthreads();
    float l0 = 0.f, l1 = 0.f, l2 = 0.f, l3 = 0.f;
    int e0 = tid * 4;
    for (int d = 0; d < 512; d++) {
        float xd = xv[d];
        float4 w = *(const float4*)(wg + d * 1024 + e0);
        l0 += xd * w.x; l1 += xd * w.y; l2 += xd * w.z; l3 += xd * w.w;
    }
    // max reduce
    float lm = fmaxf(fmaxf(l0, l1), fmaxf(l2, l3));
    red[tid] = lm; __syncthreads();
    for (int s = 128; s > 0; s >>= 1) { if (tid < s) red[tid] = fmaxf(red[tid], red[tid + s]); __syncthreads(); }
    float gmax = red[0]; __syncthreads();
    float e_0 = __expf(l0 - gmax), e_1 = __expf(l1 - gmax), e_2 = __expf(l2 - gmax), e_3 = __expf(l3 - gmax);
    red[tid] = e_0 + e_1 + e_2 + e_3; __syncthreads();
    for (int s = 128; s > 0; s >>= 1) { if (tid < s) red[tid] += red[tid + s]; __syncthreads(); }
    float inv = 1.f / red[0]; __syncthreads();
    atomicAdd(&g_rawsum[b * 1024 + e0],     e_0 * inv);
    atomicAdd(&g_rawsum[b * 1024 + e0 + 1], e_1 * inv);
    atomicAdd(&g_rawsum[b * 1024 + e0 + 2], e_2 * inv);
    atomicAdd(&g_rawsum[b * 1024 + e0 + 3], e_3 * inv);
    // top1 (on logits; same argmax as softmax, first-index wins ties)
    float bv = l0; int bi = e0;
    if (l1 > bv) { bv = l1; bi = e0 + 1; }
    if (l2 > bv) { bv = l2; bi = e0 + 2; }
    if (l3 > bv) { bv = l3; bi = e0 + 3; }
    red[tid] = bv; redi[tid] = bi; __syncthreads();
    for (int s = 128; s > 0; s >>= 1) {
        if (tid < s) {
            float ov = red[tid + s]; int oi = redi[tid + s];
            if (ov > red[tid] || (ov == red[tid] && oi < redi[tid])) { red[tid] = ov; redi[tid] = oi; }
        }
        __syncthreads();
    }
    float v1 = red[0]; int i1 = redi[0]; __syncthreads();
    // top2 (mask top1)
    float m0 = l0, m1 = l1, m2 = l2, m3 = l3;
    if      (i1 == e0)     m0 = -3e38f;
    else if (i1 == e0 + 1) m1 = -3e38f;
    else if (i1 == e0 + 2) m2 = -3e38f;
    else if (i1 == e0 + 3) m3 = -3e38f;
    bv = m0; bi = e0;
    if (m1 > bv) { bv = m1; bi = e0 + 1; }
    if (m2 > bv) { bv = m2; bi = e0 + 2; }
    if (m3 > bv) { bv = m3; bi = e0 + 3; }
    red[tid] = bv; redi[tid] = bi; __syncthreads();
    for (int s = 128; s > 0; s >>= 1) {
        if (tid < s) {
            float ov = red[tid + s]; int oi = redi[tid + s];
            if (ov > red[tid] || (ov == red[tid] && oi < redi[tid])) { red[tid] = ov; redi[tid] = oi; }
        }
        __syncthreads();
    }
    if (tid == 0) {
        float v2 = red[0]; int i2 = redi[0];
        float ga = __expf(v1 - gmax) * inv;
        float gb = __expf(v2 - gmax) * inv;
        float den = ga + gb + 1e-9f;
        g_idx1[t] = i1; g_idx2[t] = i2;
        g_g1[t] = ga / den; g_g2[t] = gb / den;
    }
}

// ---------------- capacity walk: serial per batch, exactly lucidrains Top2Gating semantics ----------------
__global__ void cap_k() {
    __shared__ int c1[1024], c2[1024];
    int b = blockIdx.x;
    for (int i = threadIdx.x; i < 1024; i += 256) { c1[i] = 0; c2[i] = 0; }
    __syncthreads();
    if (threadIdx.x == 0) {
        for (int n = 0; n < 256; n++) {
            int t = b * 256 + n; int e = g_idx1[t];
            if (c1[e] >= 4) g_g1[t] = 0.f;
            c1[e]++;
        }
        for (int n = 0; n < 256; n++) {
            int t = b * 256 + n; int e = g_idx2[t];
            int p = c2[e] + min(c1[e], 4);   // offset by FINAL capped m1 count
            if (p >= 4) g_g2[t] = 0.f;
            c2[e]++;
        }
    }
    __syncthreads();
    for (int i = threadIdx.x; i < 1024; i += 256) g_cnt1[b * 1024 + i] = c1[i];
}

// ---------------- aux loss ----------------
__global__ void loss_k(float* __restrict__ aux) {
    __shared__ float red[256];
    float s = 0.f;
    for (int i = threadIdx.x; i < Bb * Ee; i += 256) s += g_rawsum[i] * (float)g_cnt1[i];
    red[threadIdx.x] = s; __syncthreads();
    for (int st = 128; st > 0; st >>= 1) { if (threadIdx.x < st) red[threadIdx.x] += red[threadIdx.x + st]; __syncthreads(); }
    if (threadIdx.x == 0) *aux = red[0] * (0.01f * (float)Ee / ((float)Bb * 256.f * 256.f));
}

// ---------------- MoE expert compute: block per token, top-2 experts directly ----------------
__global__ __launch_bounds__(256) void moe_k(const float* __restrict__ X, const float* __restrict__ w1,
                                             const float* __restrict__ w2, float* __restrict__ out,
                                             float* __restrict__ out2) {
    __shared__ float xv[512];
    __shared__ float hs[32];
    int t = blockIdx.x, tid = threadIdx.x;
    for (int i = tid; i < 512; i += 256) xv[i] = X[t * 512 + i];
    __syncthreads();
    float acc0 = 0.f, acc1 = 0.f;
    for (int a = 0; a < 2; a++) {
        float g = a ? g_g2[t] : g_g1[t];
        int   e = a ? g_idx2[t] : g_idx1[t];
        if (g != 0.f) {              // block-uniform branch
            if (tid < 32) {
                float hv = 0.f;
                const float* wp = w1 + ((size_t)e * 512) * 32 + tid;
                #pragma unroll 8
                for (int d = 0; d < 512; d++) hv += xv[d] * wp[d * 32];
                hs[tid] = gelu_f(hv);
            }
            __syncthreads();
            float s0 = 0.f, s1 = 0.f;
            const float* wq = w2 + (size_t)e * 32 * 512;
            #pragma unroll
            for (int j = 0; j < 32; j++) {
                float h = hs[j];
                s0 += h * wq[j * 512 + tid];
                s1 += h * wq[j * 512 + tid + 256];
            }
            acc0 += g * s0; acc1 += g * s1;
            __syncthreads();
        }
    }
    out[t * 512 + tid] = acc0;        out[t * 512 + tid + 256] = acc1;
    out2[t * 512 + tid] = acc0;       out2[t * 512 + tid + 256] = acc1;
}

// ---------------- max pool k=3 s=2 pad=1 ----------------
__global__ void pool_k(const float* __restrict__ y0, float* __restrict__ out) {
    int i = blockIdx.x * 256 + threadIdx.x;   // over Bb*512*256
    int j = i & 255, bc = i >> 8;
    const float* r = y0 + bc * 512;
    int l = 2 * j;
    float m = r[l];
    if (l > 0) m = fmaxf(m, r[l - 1]);
    m = fmaxf(m, r[l + 1]);
    out[i] = m;
}

// ---------------- launch ----------------
extern "C" void kernel_launch(void* const* d_in, const int* in_sizes, int n_in,
                              void* d_out, int out_size) {
    const float* x       = (const float*)d_in[0];
    const float* emb     = (const float*)d_in[1];
    const float* r1g1s   = (const float*)d_in[2];
    const float* r1g1b   = (const float*)d_in[3];
    const float* r1c1w   = (const float*)d_in[4];
    const float* r1c1b   = (const float*)d_in[5];
    const float* r1g2s   = (const float*)d_in[6];
    const float* r1g2b   = (const float*)d_in[7];
    const float* r1c2w   = (const float*)d_in[8];
    const float* r1c2b   = (const float*)d_in[9];
    const float* r2g1s   = (const float*)d_in[10];
    const float* r2g1b   = (const float*)d_in[11];
    const float* r2c1w   = (const float*)d_in[12];
    const float* r2c1b   = (const float*)d_in[13];
    const float* r2g2s   = (const float*)d_in[14];
    const float* r2g2b   = (const float*)d_in[15];
    const float* r2c2w   = (const float*)d_in[16];
    const float* r2c2b   = (const float*)d_in[17];
    const float* aw1     = (const float*)d_in[18];
    const float* ab1     = (const float*)d_in[19];
    const float* aw2     = (const float*)d_in[20];
    const float* ab2     = (const float*)d_in[21];
    const float* mwg     = (const float*)d_in[22];
    const float* mw1     = (const float*)d_in[23];
    const float* mw2     = (const float*)d_in[24];
    const float* ow      = (const float*)d_in[25];
    const float* ob      = (const float*)d_in[26];
    float* out = (float*)d_out;

    float *S1, *S2, *S3, *T;
    cudaGetSymbolAddress((void**)&S1, g_S1);
    cudaGetSymbolAddress((void**)&S2, g_S2);
    cudaGetSymbolAddress((void**)&S3, g_S3);
    cudaGetSymbolAddress((void**)&T,  g_T);

    cudaFuncSetAttribute(attn_k, cudaFuncAttributeMaxDynamicSharedMemorySize, 131072);

    // res_block 1
    add_k<<<4096, 256>>>(x, emb, S1);
    gnstats_k<<<256, 256>>>(S1);
    gngelu_k<<<4096, 256>>>(S1, r1g1s, r1g1b, S2);
    conv3_k<<<dim3(4, 64, 8), 128>>>(S2, r1c1w, r1c1b, nullptr, S3, 256);
    gnstats_k<<<256, 256>>>(S3);
    gngelu_k<<<4096, 256>>>(S3, r1g2s, r1g2b, S2);
    conv3_k<<<dim3(4, 64, 8), 128>>>(S2, r1c2w, r1c2b, S1, S3, 256);

    // attention
    qkv_k<<<dim3(8, 16), 256>>>(S3, aw1, ab1, T);
    attn_k<<<dim3(8, 8), 512, 131072>>>(T, S2);
    oproj_k<<<dim3(8, 16), 256>>>(S2, aw2, ab2, emb, S1);   // fuses res_block2's +emb

    // res_block 2
    gnstats_k<<<256, 256>>>(S1);
    gngelu_k<<<4096, 256>>>(S1, r2g1s, r2g1b, S2);
    conv3_k<<<dim3(4, 64, 8), 128>>>(S2, r2c1w, r2c1b, nullptr, S3, 256);
    gnstats_k<<<256, 256>>>(S3);
    gngelu_k<<<4096, 256>>>(S3, r2g2s, r2g2b, S2);
    conv3_k<<<dim3(4, 64, 8), 128>>>(S2, r2c2w, r2c2b, S1, S3, 256);

    // MoE
    zero_k<<<32, 256>>>();
    gate_k<<<2048, 256>>>(S3, mwg);
    cap_k<<<8, 256>>>();
    loss_k<<<1, 256>>>(out + 2 * 1048576);
    moe_k<<<2048, 256>>>(S3, mw1, mw2, S2, out + 1048576);

    // output conv + maxpool
    conv3_k<<<dim3(4, 128, 8), 128>>>(S2, ow, ob, nullptr, T, 512);
    pool_k<<<4096, 256>>>(T, out);
}